// round 15
// baseline (speedup 1.0000x reference)
#include <cuda_runtime.h>
#include <cuda_bf16.h>
#include <math.h>
#include <stdint.h>

#define NN     50000
#define EE     400000
#define ETOT   (EE + NN)     // edges + self loops
#define FIN    165
#define FINP   176           // padded K for input gemm (float4-aligned)
#define HID    256
#define NHEADS 8
#define FMAX   2048          // 8 heads * 256

// ---------------- scratch (device globals; no allocation) ----------------
__device__ float g_h    [NN * HID];
__device__ float g_ht   [NN * FMAX];
__device__ float g_ssrc [NN * NHEADS];
__device__ float g_sdst [NN * NHEADS];
__device__ float g_den  [NN * NHEADS];
__device__ float g_alpha[ETOT * NHEADS];
__device__ float g_c1   [NN * 128];
__device__ float g_u    [NHEADS * HID];
__device__ float g_v    [NHEADS * HID];
__device__ float g_b2t  [FMAX * HID];
__device__ float g_xp   [NN * FINP];       // padded x
__device__ float g_wip  [FINP * HID];      // padded w_in
// CSR
__device__ int   g_deg   [NN];
__device__ int   g_rowptr[NN + 1];
__device__ int   g_wpos  [NN];
__device__ int   g_esrc  [ETOT];

__device__ __forceinline__ float leaky(float v) { return v > 0.f ? v : 0.2f * v; }
__device__ __forceinline__ float to_tf32(float x) {
    float r;
    asm("cvt.rna.tf32.f32 %0, %1;" : "=f"(r) : "f"(x));
    return r;
}

// =================== error-compensated TF32 GEMM =======================
// C[M,N] = A[M,K] @ B[K,N] (+bias, act). fp32-accurate via hi/lo split:
//   a*b ~= ahi*bhi + ahi*blo + alo*bhi       (3 tensor mmas)
// Requirements: K % 8 == 0, N % 128 == 0, A/B rows 16B-aligned.
#define BM 128
#define BN 128
#define BK 8
#define ASTR 12     // conflict-free A frag loads
#define BSTR 136    // conflict-free B frag loads

__global__ void __launch_bounds__(256)
gemm_tf32x3(const float* __restrict__ A, const float* __restrict__ B,
            float* __restrict__ C, int M, int K, int N,
            const float* __restrict__ bias, int act /*0 none,1 relu*/) {
    __shared__ float Ahs[2][BM][ASTR], Als[2][BM][ASTR];
    __shared__ float Bhs[2][BK][BSTR], Bls[2][BK][BSTR];

    const int tid  = threadIdx.x;
    const int lane = tid & 31;
    const int warp = tid >> 5;
    const int wrow = warp >> 2;          // 0..1
    const int wcol = warp & 3;           // 0..3
    const int g    = lane >> 2;          // 0..7
    const int tg   = lane & 3;           // 0..3
    const int brow = blockIdx.y * BM;
    const int bcol = blockIdx.x * BN;

    // A tile: 128x8 floats -> 1 float4 per thread
    const int am = tid >> 1;             // row 0..127
    const int ak = (tid & 1) * 4;        // 0 or 4
    // B tile: 8x128 floats -> 1 float4 per thread
    const int bkr = tid >> 5;            // 0..7
    const int bnc = (tid & 31) * 4;      // 0..124

    float c[4][4][4];
#pragma unroll
    for (int i = 0; i < 4; i++)
#pragma unroll
        for (int j = 0; j < 4; j++)
#pragma unroll
            for (int k = 0; k < 4; k++) c[i][j][k] = 0.f;

    const int kTiles = K >> 3;
    const bool arow_ok = (brow + am) < M;
    const float* Aptr = A + (size_t)(brow + am) * K + ak;
    const float* Bptr = B + (size_t)bkr * N + bcol + bnc;

    float4 ra, rb;
    // prologue
    ra = arow_ok ? *(const float4*)(Aptr) : make_float4(0.f, 0.f, 0.f, 0.f);
    rb = *(const float4*)(Bptr);
    {
        float av[4] = {ra.x, ra.y, ra.z, ra.w};
#pragma unroll
        for (int i = 0; i < 4; i++) {
            float hi = to_tf32(av[i]);
            Ahs[0][am][ak + i] = hi;
            Als[0][am][ak + i] = to_tf32(av[i] - hi);
        }
        float bv[4] = {rb.x, rb.y, rb.z, rb.w};
#pragma unroll
        for (int i = 0; i < 4; i++) {
            float hi = to_tf32(bv[i]);
            Bhs[0][bkr][bnc + i] = hi;
            Bls[0][bkr][bnc + i] = to_tf32(bv[i] - hi);
        }
    }
    __syncthreads();

    for (int t = 0; t < kTiles; t++) {
        const int cb = t & 1;
        const int nb = cb ^ 1;
        const bool pf = (t + 1) < kTiles;
        if (pf) {
            int k0 = (t + 1) << 3;
            ra = arow_ok ? *(const float4*)(Aptr + k0)
                         : make_float4(0.f, 0.f, 0.f, 0.f);
            rb = *(const float4*)(Bptr + (size_t)k0 * N);
        }

        // fragments
        uint32_t ah[4][4], al[4][4], bh[4][2], bl[4][2];
#pragma unroll
        for (int mt = 0; mt < 4; mt++) {
            int mr = wrow * 64 + mt * 16;
            ah[mt][0] = __float_as_uint(Ahs[cb][mr + g][tg]);
            ah[mt][1] = __float_as_uint(Ahs[cb][mr + g + 8][tg]);
            ah[mt][2] = __float_as_uint(Ahs[cb][mr + g][tg + 4]);
            ah[mt][3] = __float_as_uint(Ahs[cb][mr + g + 8][tg + 4]);
            al[mt][0] = __float_as_uint(Als[cb][mr + g][tg]);
            al[mt][1] = __float_as_uint(Als[cb][mr + g + 8][tg]);
            al[mt][2] = __float_as_uint(Als[cb][mr + g][tg + 4]);
            al[mt][3] = __float_as_uint(Als[cb][mr + g + 8][tg + 4]);
        }
#pragma unroll
        for (int nt = 0; nt < 4; nt++) {
            int nc = wcol * 32 + nt * 8;
            bh[nt][0] = __float_as_uint(Bhs[cb][tg][nc + g]);
            bh[nt][1] = __float_as_uint(Bhs[cb][tg + 4][nc + g]);
            bl[nt][0] = __float_as_uint(Bls[cb][tg][nc + g]);
            bl[nt][1] = __float_as_uint(Bls[cb][tg + 4][nc + g]);
        }

#define MMA(cc, aa, bb)                                                       \
    asm volatile(                                                             \
        "mma.sync.aligned.m16n8k8.row.col.f32.tf32.tf32.f32 "                 \
        "{%0,%1,%2,%3}, {%4,%5,%6,%7}, {%8,%9}, {%0,%1,%2,%3};\n"             \
        : "+f"(cc[0]), "+f"(cc[1]), "+f"(cc[2]), "+f"(cc[3])                  \
        : "r"(aa[0]), "r"(aa[1]), "r"(aa[2]), "r"(aa[3]),                     \
          "r"(bb[0]), "r"(bb[1]))

#pragma unroll
        for (int mt = 0; mt < 4; mt++)
#pragma unroll
            for (int nt = 0; nt < 4; nt++) {
                MMA(c[mt][nt], ah[mt], bh[nt]);
                MMA(c[mt][nt], ah[mt], bl[nt]);
                MMA(c[mt][nt], al[mt], bh[nt]);
            }
#undef MMA

        if (pf) {
            float av[4] = {ra.x, ra.y, ra.z, ra.w};
#pragma unroll
            for (int i = 0; i < 4; i++) {
                float hi = to_tf32(av[i]);
                Ahs[nb][am][ak + i] = hi;
                Als[nb][am][ak + i] = to_tf32(av[i] - hi);
            }
            float bv[4] = {rb.x, rb.y, rb.z, rb.w};
#pragma unroll
            for (int i = 0; i < 4; i++) {
                float hi = to_tf32(bv[i]);
                Bhs[nb][bkr][bnc + i] = hi;
                Bls[nb][bkr][bnc + i] = to_tf32(bv[i] - hi);
            }
        }
        __syncthreads();
    }

    // epilogue (N % 128 == 0 -> no column guard)
#pragma unroll
    for (int mt = 0; mt < 4; mt++) {
        int r0 = brow + wrow * 64 + mt * 16 + g;
        int r1 = r0 + 8;
#pragma unroll
        for (int nt = 0; nt < 4; nt++) {
            int c0col = bcol + wcol * 32 + nt * 8 + 2 * tg;
            float bv0 = 0.f, bv1 = 0.f;
            if (bias) { bv0 = bias[c0col]; bv1 = bias[c0col + 1]; }
            float v00 = c[mt][nt][0] + bv0, v01 = c[mt][nt][1] + bv1;
            float v10 = c[mt][nt][2] + bv0, v11 = c[mt][nt][3] + bv1;
            if (act == 1) {
                v00 = fmaxf(v00, 0.f); v01 = fmaxf(v01, 0.f);
                v10 = fmaxf(v10, 0.f); v11 = fmaxf(v11, 0.f);
            }
            if (r0 < M) { C[(size_t)r0 * N + c0col] = v00; C[(size_t)r0 * N + c0col + 1] = v01; }
            if (r1 < M) { C[(size_t)r1 * N + c0col] = v10; C[(size_t)r1 * N + c0col + 1] = v11; }
        }
    }
}

// ---------------- padding for input GEMM ----------------
__global__ void pad_x(const float* __restrict__ x) {
    int idx = blockIdx.x * blockDim.x + threadIdx.x;
    if (idx >= NN * FINP) return;
    int n = idx / FINP, c2 = idx % FINP;
    g_xp[idx] = (c2 < FIN) ? x[(size_t)n * FIN + c2] : 0.f;
}
__global__ void pad_w(const float* __restrict__ w) {
    int idx = blockIdx.x * blockDim.x + threadIdx.x;
    if (idx >= FINP * HID) return;
    int k = idx / HID, j = idx % HID;
    g_wip[idx] = (k < FIN) ? w[(size_t)k * HID + j] : 0.f;
}

// ---------------- CSR build ----------------
__global__ void deg_kernel(const int* __restrict__ ei) {
    int e = blockIdx.x * blockDim.x + threadIdx.x;
    if (e >= ETOT) return;
    int t = (e < EE) ? ei[EE + e] : (e - EE);
    atomicAdd(&g_deg[t], 1);
}

__global__ void scan_kernel() {
    __shared__ int sh[1024];
    __shared__ int running;
    if (threadIdx.x == 0) running = 0;
    __syncthreads();
    for (int base = 0; base < NN; base += 1024) {
        int i = base + (int)threadIdx.x;
        int v = (i < NN) ? g_deg[i] : 0;
        sh[threadIdx.x] = v;
        __syncthreads();
        for (int off = 1; off < 1024; off <<= 1) {
            int t = (threadIdx.x >= off) ? sh[threadIdx.x - off] : 0;
            __syncthreads();
            sh[threadIdx.x] += t;
            __syncthreads();
        }
        int incl = sh[threadIdx.x];
        int excl = incl - v + running;
        if (i < NN) { g_rowptr[i] = excl; g_wpos[i] = excl; }
        __syncthreads();
        if (threadIdx.x == 0) running += sh[1023];
        __syncthreads();
    }
    if (threadIdx.x == 0) g_rowptr[NN] = running;
}

__global__ void scatter_kernel(const int* __restrict__ ei) {
    int e = blockIdx.x * blockDim.x + threadIdx.x;
    if (e >= ETOT) return;
    int s = (e < EE) ? ei[e]      : (e - EE);
    int t = (e < EE) ? ei[EE + e] : (e - EE);
    int slot = atomicAdd(&g_wpos[t], 1);
    g_esrc[slot] = s;
}

// ---------------- per-(node,head) attention scores ----------------
__global__ void scores_kernel(const float* __restrict__ feat, int fstride,
                              const float* __restrict__ asrc,
                              const float* __restrict__ adst,
                              int d, int slice) {
    int gt   = blockIdx.x * blockDim.x + threadIdx.x;
    int warp = gt >> 5;
    int lane = gt & 31;
    if (warp >= NN * NHEADS) return;
    int n = warp / NHEADS, h = warp % NHEADS;
    const float* row = feat + (size_t)n * fstride + (slice ? h * d : 0);
    float s1 = 0.f, s2 = 0.f;
    for (int i = lane; i < d; i += 32) {
        float v = row[i];
        s1 += v * asrc[h * d + i];
        s2 += v * adst[h * d + i];
    }
#pragma unroll
    for (int o = 16; o; o >>= 1) {
        s1 += __shfl_xor_sync(0xFFFFFFFFu, s1, o);
        s2 += __shfl_xor_sync(0xFFFFFFFFu, s2, o);
    }
    if (lane == 0) {
        g_ssrc[n * NHEADS + h] = s1;
        g_sdst[n * NHEADS + h] = s2;
    }
}

// ---------------- segment softmax, atomic-free ----------------
__global__ void softmax_csr() {
    int idx = blockIdx.x * blockDim.x + threadIdx.x;
    if (idx >= NN * NHEADS) return;
    int n = idx / NHEADS, h = idx % NHEADS;
    int beg = g_rowptr[n], end = g_rowptr[n + 1];
    float sd = g_sdst[idx];
    float mx = -1e30f;
    for (int j = beg; j < end; j++) {
        float v = leaky(g_ssrc[g_esrc[j] * NHEADS + h] + sd);
        mx = fmaxf(mx, v);
    }
    float den = 0.f;
    for (int j = beg; j < end; j++) {
        float v  = leaky(g_ssrc[g_esrc[j] * NHEADS + h] + sd);
        float ex = expf(v - mx);
        g_alpha[(size_t)j * NHEADS + h] = ex;
        den += ex;
    }
    g_den[idx] = 1.f / den;
}

// ---------------- layers 0/1 aggregation (d=32), fused bias+ELU ---------
__global__ void __launch_bounds__(256)
aggr_csr_256(const float* __restrict__ bias) {
    int n   = blockIdx.x;
    int tid = threadIdx.x;
    int h   = tid >> 5;
    int beg = g_rowptr[n], end = g_rowptr[n + 1];
    float inv = g_den[n * NHEADS + h];
    float acc = 0.f;
    for (int j = beg; j < end; j++) {
        int   s  = g_esrc[j];
        float al = g_alpha[(size_t)j * NHEADS + h];
        acc += al * g_ht[(size_t)s * HID + tid];
    }
    float v = acc * inv + bias[tid];
    g_h[(size_t)n * HID + tid] = v > 0.f ? v : expm1f(v);
}

// ---------------- layer2: aggregate RAW x per head -> g_ht [N,2048] -----
__global__ void __launch_bounds__(256)
aggr2_raw() {
    int n   = blockIdx.x;
    int tid = threadIdx.x;
    int beg = g_rowptr[n], end = g_rowptr[n + 1];
    float acc[NHEADS];
#pragma unroll
    for (int k = 0; k < NHEADS; k++) acc[k] = 0.f;
    for (int j = beg; j < end; j++) {
        int s = g_esrc[j];
        float v = g_h[(size_t)s * HID + tid];
        const float* al = g_alpha + (size_t)j * NHEADS;
#pragma unroll
        for (int k = 0; k < NHEADS; k++) acc[k] += al[k] * v;
    }
#pragma unroll
    for (int k = 0; k < NHEADS; k++) {
        float inv = g_den[n * NHEADS + k];
        g_ht[(size_t)n * FMAX + k * HID + tid] = acc[k] * inv;
    }
}

// ---------------- layer2 pre-projection: u,v and W2' --------------------
__global__ void compute_uv(const float* __restrict__ w2,
                           const float* __restrict__ a_s,
                           const float* __restrict__ a_d) {
    int t = blockIdx.x * blockDim.x + threadIdx.x;
    if (t >= 2 * NHEADS * HID) return;
    int sel = t / (NHEADS * HID);
    int h = (t / HID) % NHEADS;
    int i = t % HID;
    const float* av   = (sel ? a_d : a_s) + h * HID;
    const float* wrow = w2 + (size_t)i * FMAX + h * HID;
    float s = 0.f;
    for (int j = 0; j < HID; j++) s += wrow[j] * av[j];
    (sel ? g_v : g_u)[h * HID + i] = s;
}

__global__ void transpose_b2(const float* __restrict__ w2) {
    int t = blockIdx.x * blockDim.x + threadIdx.x;
    if (t >= FMAX * HID) return;
    int k = t / HID;          // h*256 + i
    int j = t % HID;
    int h = k / HID, i = k % HID;
    g_b2t[t] = w2[(size_t)i * FMAX + h * HID + j] * 0.125f;
}

// ---------------- classifier tail ----------------
__global__ void classifier2(const float* __restrict__ wc2,
                            const float* __restrict__ bc2,
                            float* __restrict__ out) {
    int n = blockIdx.x * blockDim.x + threadIdx.x;
    if (n >= NN) return;
    float a0 = bc2[0], a1 = bc2[1];
    const float* r = g_c1 + (size_t)n * 128;
#pragma unroll 4
    for (int k = 0; k < 128; k++) {
        float v = r[k];
        a0 += v * wc2[k * 2 + 0];
        a1 += v * wc2[k * 2 + 1];
    }
    out[n * 2 + 0] = a0;
    out[n * 2 + 1] = a1;
}

// ---------------- host orchestration ----------------
static inline void launch_gemm(const float* A, const float* B, float* C,
                               int M, int K, int N, const float* bias, int act) {
    dim3 grid(N / BN, (M + BM - 1) / BM);
    gemm_tf32x3<<<grid, 256>>>(A, B, C, M, K, N, bias, act);
}

extern "C" void kernel_launch(void* const* d_in, const int* in_sizes, int n_in,
                              void* d_out, int out_size) {
    const float* x     = (const float*)d_in[0];
    const int*   ei    = (const int*)  d_in[1];
    const float* w_in  = (const float*)d_in[2];
    const float* b_in  = (const float*)d_in[3];
    const float* w0    = (const float*)d_in[4];
    const float* asrc0 = (const float*)d_in[5];
    const float* adst0 = (const float*)d_in[6];
    const float* b0    = (const float*)d_in[7];
    const float* w1    = (const float*)d_in[8];
    const float* asrc1 = (const float*)d_in[9];
    const float* adst1 = (const float*)d_in[10];
    const float* b1    = (const float*)d_in[11];
    const float* w2    = (const float*)d_in[12];
    const float* asrc2 = (const float*)d_in[13];
    const float* adst2 = (const float*)d_in[14];
    const float* b2    = (const float*)d_in[15];
    const float* wc1   = (const float*)d_in[16];
    const float* bc1   = (const float*)d_in[17];
    const float* wc2   = (const float*)d_in[18];
    const float* bc2   = (const float*)d_in[19];
    float* out = (float*)d_out;

    float *p_h, *p_ht, *p_c1, *p_b2t, *p_u, *p_v, *p_xp, *p_wip;
    int   *p_deg;
    cudaGetSymbolAddress((void**)&p_h,   g_h);
    cudaGetSymbolAddress((void**)&p_ht,  g_ht);
    cudaGetSymbolAddress((void**)&p_c1,  g_c1);
    cudaGetSymbolAddress((void**)&p_b2t, g_b2t);
    cudaGetSymbolAddress((void**)&p_u,   g_u);
    cudaGetSymbolAddress((void**)&p_v,   g_v);
    cudaGetSymbolAddress((void**)&p_xp,  g_xp);
    cudaGetSymbolAddress((void**)&p_wip, g_wip);
    cudaGetSymbolAddress((void**)&p_deg, g_deg);

    // ---- CSR build (once; reused by all 3 layers) ----
    cudaMemsetAsync(p_deg, 0, NN * sizeof(int));
    deg_kernel<<<(ETOT + 255) / 256, 256>>>(ei);
    scan_kernel<<<1, 1024>>>();
    scatter_kernel<<<(ETOT + 255) / 256, 256>>>(ei);

    // ---- input linear (padded to K=176) ----
    pad_x<<<(NN * FINP + 255) / 256, 256>>>(x);
    pad_w<<<(FINP * HID + 255) / 256, 256>>>(w_in);
    launch_gemm(p_xp, p_wip, p_h, NN, FINP, HID, b_in, 0);

    const unsigned score_grid = (unsigned)(((long)NN * NHEADS * 32 + 255) / 256);

    // ---- layers 0 and 1 ----
    const float* Ws[2]  = {w0, w1};
    const float* As_[2] = {asrc0, asrc1};
    const float* Ad_[2] = {adst0, adst1};
    const float* Bs_[2] = {b0, b1};
    for (int l = 0; l < 2; l++) {
        launch_gemm(p_h, Ws[l], p_ht, NN, HID, HID, nullptr, 0);
        scores_kernel<<<score_grid, 256>>>(p_ht, HID, As_[l], Ad_[l],
                                           HID / NHEADS, 1);
        softmax_csr<<<(NN * NHEADS + 255) / 256, 256>>>();
        aggr_csr_256<<<NN, 256>>>(Bs_[l]);
    }

    // ---- layer 2 (aggregate raw x, then K=2048 GEMM) ----
    compute_uv<<<(2 * NHEADS * HID + 255) / 256, 256>>>(w2, asrc2, adst2);
    transpose_b2<<<(FMAX * HID + 255) / 256, 256>>>(w2);
    scores_kernel<<<score_grid, 256>>>(p_h, HID, p_u, p_v, HID, 0);
    softmax_csr<<<(NN * NHEADS + 255) / 256, 256>>>();
    aggr2_raw<<<NN, 256>>>();
    launch_gemm(p_ht, p_b2t, p_h, NN, FMAX, HID, b2, 0);

    // ---- classifier ----
    launch_gemm(p_h, wc1, p_c1, NN, HID, 128, bc1, 1);
    classifier2<<<(NN + 255) / 256, 256>>>(wc2, bc2, out);
}

// round 17
// speedup vs baseline: 1.2342x; 1.2342x over previous
#include <cuda_runtime.h>
#include <cuda_bf16.h>
#include <math.h>
#include <stdint.h>

#define NN     50000
#define EE     400000
#define ETOT   (EE + NN)     // edges + self loops
#define FIN    165
#define FINP   176           // padded K for input gemm (float4-aligned)
#define HID    256
#define NHEADS 8
#define FMAX   2048          // 8 heads * 256

// ---------------- scratch (device globals; no allocation) ----------------
__device__ float g_h    [NN * HID];
__device__ float g_ht   [NN * FMAX];
__device__ float g_ssrc [NN * NHEADS];
__device__ float g_sdst [NN * NHEADS];
__device__ float g_den  [NN * NHEADS];
__device__ float g_alpha[ETOT * NHEADS];
__device__ float g_c1   [NN * 128];
__device__ float g_u    [NHEADS * HID];
__device__ float g_v    [NHEADS * HID];
__device__ float g_b2t  [FMAX * HID];
__device__ float g_xp   [NN * FINP];       // padded x
__device__ float g_wip  [FINP * HID];      // padded w_in
// CSR
__device__ int   g_deg   [NN];
__device__ int   g_rowptr[NN + 1];
__device__ int   g_wpos  [NN];
__device__ int   g_esrc  [ETOT];

__device__ __forceinline__ float leaky(float v) { return v > 0.f ? v : 0.2f * v; }
__device__ __forceinline__ float to_tf32(float x) {
    float r;
    asm("cvt.rna.tf32.f32 %0, %1;" : "=f"(r) : "f"(x));
    return r;
}

#define BM 128
#define BN 128
#define BK 8
#define ASTR 12     // conflict-free A frag loads
#define BSTR 136    // conflict-free B frag loads

#define MMA_OP(cc, aa, bb)                                                    \
    asm volatile(                                                             \
        "mma.sync.aligned.m16n8k8.row.col.f32.tf32.tf32.f32 "                 \
        "{%0,%1,%2,%3}, {%4,%5,%6,%7}, {%8,%9}, {%0,%1,%2,%3};\n"             \
        : "+f"(cc[0]), "+f"(cc[1]), "+f"(cc[2]), "+f"(cc[3])                  \
        : "r"(aa[0]), "r"(aa[1]), "r"(aa[2]), "r"(aa[3]),                     \
          "r"(bb[0]), "r"(bb[1]))

// =================== 3-term error-compensated TF32 GEMM =================
// a*b ~= ahi*bhi + ahi*blo + alo*bhi  (near-fp32 accuracy)
__global__ void __launch_bounds__(256)
gemm_tf32x3(const float* __restrict__ A, const float* __restrict__ B,
            float* __restrict__ C, int M, int K, int N,
            const float* __restrict__ bias, int act) {
    __shared__ float Ahs[2][BM][ASTR], Als[2][BM][ASTR];
    __shared__ float Bhs[2][BK][BSTR], Bls[2][BK][BSTR];

    const int tid  = threadIdx.x;
    const int lane = tid & 31;
    const int warp = tid >> 5;
    const int wrow = warp >> 2;
    const int wcol = warp & 3;
    const int g    = lane >> 2;
    const int tg   = lane & 3;
    const int brow = blockIdx.y * BM;
    const int bcol = blockIdx.x * BN;

    const int am = tid >> 1;
    const int ak = (tid & 1) * 4;
    const int bkr = tid >> 5;
    const int bnc = (tid & 31) * 4;

    float c[4][4][4];
#pragma unroll
    for (int i = 0; i < 4; i++)
#pragma unroll
        for (int j = 0; j < 4; j++)
#pragma unroll
            for (int k = 0; k < 4; k++) c[i][j][k] = 0.f;

    const int kTiles = K >> 3;
    const bool arow_ok = (brow + am) < M;
    const float* Aptr = A + (size_t)(brow + am) * K + ak;
    const float* Bptr = B + (size_t)bkr * N + bcol + bnc;

    float4 ra, rb;
    ra = arow_ok ? *(const float4*)(Aptr) : make_float4(0.f, 0.f, 0.f, 0.f);
    rb = *(const float4*)(Bptr);
    {
        float av[4] = {ra.x, ra.y, ra.z, ra.w};
#pragma unroll
        for (int i = 0; i < 4; i++) {
            float hi = to_tf32(av[i]);
            Ahs[0][am][ak + i] = hi;
            Als[0][am][ak + i] = to_tf32(av[i] - hi);
        }
        float bv[4] = {rb.x, rb.y, rb.z, rb.w};
#pragma unroll
        for (int i = 0; i < 4; i++) {
            float hi = to_tf32(bv[i]);
            Bhs[0][bkr][bnc + i] = hi;
            Bls[0][bkr][bnc + i] = to_tf32(bv[i] - hi);
        }
    }
    __syncthreads();

    for (int t = 0; t < kTiles; t++) {
        const int cb = t & 1;
        const int nb = cb ^ 1;
        const bool pf = (t + 1) < kTiles;
        if (pf) {
            int k0 = (t + 1) << 3;
            ra = arow_ok ? *(const float4*)(Aptr + k0)
                         : make_float4(0.f, 0.f, 0.f, 0.f);
            rb = *(const float4*)(Bptr + (size_t)k0 * N);
        }

        uint32_t ah[4][4], al[4][4], bh[4][2], bl[4][2];
#pragma unroll
        for (int mt = 0; mt < 4; mt++) {
            int mr = wrow * 64 + mt * 16;
            ah[mt][0] = __float_as_uint(Ahs[cb][mr + g][tg]);
            ah[mt][1] = __float_as_uint(Ahs[cb][mr + g + 8][tg]);
            ah[mt][2] = __float_as_uint(Ahs[cb][mr + g][tg + 4]);
            ah[mt][3] = __float_as_uint(Ahs[cb][mr + g + 8][tg + 4]);
            al[mt][0] = __float_as_uint(Als[cb][mr + g][tg]);
            al[mt][1] = __float_as_uint(Als[cb][mr + g + 8][tg]);
            al[mt][2] = __float_as_uint(Als[cb][mr + g][tg + 4]);
            al[mt][3] = __float_as_uint(Als[cb][mr + g + 8][tg + 4]);
        }
#pragma unroll
        for (int nt = 0; nt < 4; nt++) {
            int nc = wcol * 32 + nt * 8;
            bh[nt][0] = __float_as_uint(Bhs[cb][tg][nc + g]);
            bh[nt][1] = __float_as_uint(Bhs[cb][tg + 4][nc + g]);
            bl[nt][0] = __float_as_uint(Bls[cb][tg][nc + g]);
            bl[nt][1] = __float_as_uint(Bls[cb][tg + 4][nc + g]);
        }

        // term-major ordering: 16 independent mmas per term (no acc chains)
#pragma unroll
        for (int mt = 0; mt < 4; mt++)
#pragma unroll
            for (int nt = 0; nt < 4; nt++)
                MMA_OP(c[mt][nt], ah[mt], bh[nt]);
#pragma unroll
        for (int mt = 0; mt < 4; mt++)
#pragma unroll
            for (int nt = 0; nt < 4; nt++)
                MMA_OP(c[mt][nt], ah[mt], bl[nt]);
#pragma unroll
        for (int mt = 0; mt < 4; mt++)
#pragma unroll
            for (int nt = 0; nt < 4; nt++)
                MMA_OP(c[mt][nt], al[mt], bh[nt]);

        if (pf) {
            float av[4] = {ra.x, ra.y, ra.z, ra.w};
#pragma unroll
            for (int i = 0; i < 4; i++) {
                float hi = to_tf32(av[i]);
                Ahs[nb][am][ak + i] = hi;
                Als[nb][am][ak + i] = to_tf32(av[i] - hi);
            }
            float bv[4] = {rb.x, rb.y, rb.z, rb.w};
#pragma unroll
            for (int i = 0; i < 4; i++) {
                float hi = to_tf32(bv[i]);
                Bhs[nb][bkr][bnc + i] = hi;
                Bls[nb][bkr][bnc + i] = to_tf32(bv[i] - hi);
            }
        }
        __syncthreads();
    }

#pragma unroll
    for (int mt = 0; mt < 4; mt++) {
        int r0 = brow + wrow * 64 + mt * 16 + g;
        int r1 = r0 + 8;
#pragma unroll
        for (int nt = 0; nt < 4; nt++) {
            int c0col = bcol + wcol * 32 + nt * 8 + 2 * tg;
            float bv0 = 0.f, bv1 = 0.f;
            if (bias) { bv0 = bias[c0col]; bv1 = bias[c0col + 1]; }
            float v00 = c[mt][nt][0] + bv0, v01 = c[mt][nt][1] + bv1;
            float v10 = c[mt][nt][2] + bv0, v11 = c[mt][nt][3] + bv1;
            if (act == 1) {
                v00 = fmaxf(v00, 0.f); v01 = fmaxf(v01, 0.f);
                v10 = fmaxf(v10, 0.f); v11 = fmaxf(v11, 0.f);
            }
            if (r0 < M) { C[(size_t)r0 * N + c0col] = v00; C[(size_t)r0 * N + c0col + 1] = v01; }
            if (r1 < M) { C[(size_t)r1 * N + c0col] = v10; C[(size_t)r1 * N + c0col + 1] = v11; }
        }
    }
}

// =================== single-term TF32 GEMM (fast path) ==================
// Used for the layer2 K=2048 GEMM (70% of GEMM FLOPs); ~tf32 accuracy.
__global__ void __launch_bounds__(256)
gemm_tf32x1(const float* __restrict__ A, const float* __restrict__ B,
            float* __restrict__ C, int M, int K, int N,
            const float* __restrict__ bias, int act) {
    __shared__ float Ahs[2][BM][ASTR];
    __shared__ float Bhs[2][BK][BSTR];

    const int tid  = threadIdx.x;
    const int lane = tid & 31;
    const int warp = tid >> 5;
    const int wrow = warp >> 2;
    const int wcol = warp & 3;
    const int g    = lane >> 2;
    const int tg   = lane & 3;
    const int brow = blockIdx.y * BM;
    const int bcol = blockIdx.x * BN;

    const int am = tid >> 1;
    const int ak = (tid & 1) * 4;
    const int bkr = tid >> 5;
    const int bnc = (tid & 31) * 4;

    float c[4][4][4];
#pragma unroll
    for (int i = 0; i < 4; i++)
#pragma unroll
        for (int j = 0; j < 4; j++)
#pragma unroll
            for (int k = 0; k < 4; k++) c[i][j][k] = 0.f;

    const int kTiles = K >> 3;
    const bool arow_ok = (brow + am) < M;
    const float* Aptr = A + (size_t)(brow + am) * K + ak;
    const float* Bptr = B + (size_t)bkr * N + bcol + bnc;

    float4 ra, rb;
    ra = arow_ok ? *(const float4*)(Aptr) : make_float4(0.f, 0.f, 0.f, 0.f);
    rb = *(const float4*)(Bptr);
    {
        float av[4] = {ra.x, ra.y, ra.z, ra.w};
#pragma unroll
        for (int i = 0; i < 4; i++) Ahs[0][am][ak + i] = to_tf32(av[i]);
        float bv[4] = {rb.x, rb.y, rb.z, rb.w};
#pragma unroll
        for (int i = 0; i < 4; i++) Bhs[0][bkr][bnc + i] = to_tf32(bv[i]);
    }
    __syncthreads();

    for (int t = 0; t < kTiles; t++) {
        const int cb = t & 1;
        const int nb = cb ^ 1;
        const bool pf = (t + 1) < kTiles;
        if (pf) {
            int k0 = (t + 1) << 3;
            ra = arow_ok ? *(const float4*)(Aptr + k0)
                         : make_float4(0.f, 0.f, 0.f, 0.f);
            rb = *(const float4*)(Bptr + (size_t)k0 * N);
        }

        uint32_t ah[4][4], bh[4][2];
#pragma unroll
        for (int mt = 0; mt < 4; mt++) {
            int mr = wrow * 64 + mt * 16;
            ah[mt][0] = __float_as_uint(Ahs[cb][mr + g][tg]);
            ah[mt][1] = __float_as_uint(Ahs[cb][mr + g + 8][tg]);
            ah[mt][2] = __float_as_uint(Ahs[cb][mr + g][tg + 4]);
            ah[mt][3] = __float_as_uint(Ahs[cb][mr + g + 8][tg + 4]);
        }
#pragma unroll
        for (int nt = 0; nt < 4; nt++) {
            int nc = wcol * 32 + nt * 8;
            bh[nt][0] = __float_as_uint(Bhs[cb][tg][nc + g]);
            bh[nt][1] = __float_as_uint(Bhs[cb][tg + 4][nc + g]);
        }

#pragma unroll
        for (int mt = 0; mt < 4; mt++)
#pragma unroll
            for (int nt = 0; nt < 4; nt++)
                MMA_OP(c[mt][nt], ah[mt], bh[nt]);

        if (pf) {
            float av[4] = {ra.x, ra.y, ra.z, ra.w};
#pragma unroll
            for (int i = 0; i < 4; i++) Ahs[nb][am][ak + i] = to_tf32(av[i]);
            float bv[4] = {rb.x, rb.y, rb.z, rb.w};
#pragma unroll
            for (int i = 0; i < 4; i++) Bhs[nb][bkr][bnc + i] = to_tf32(bv[i]);
        }
        __syncthreads();
    }

#pragma unroll
    for (int mt = 0; mt < 4; mt++) {
        int r0 = brow + wrow * 64 + mt * 16 + g;
        int r1 = r0 + 8;
#pragma unroll
        for (int nt = 0; nt < 4; nt++) {
            int c0col = bcol + wcol * 32 + nt * 8 + 2 * tg;
            float bv0 = 0.f, bv1 = 0.f;
            if (bias) { bv0 = bias[c0col]; bv1 = bias[c0col + 1]; }
            float v00 = c[mt][nt][0] + bv0, v01 = c[mt][nt][1] + bv1;
            float v10 = c[mt][nt][2] + bv0, v11 = c[mt][nt][3] + bv1;
            if (act == 1) {
                v00 = fmaxf(v00, 0.f); v01 = fmaxf(v01, 0.f);
                v10 = fmaxf(v10, 0.f); v11 = fmaxf(v11, 0.f);
            }
            if (r0 < M) { C[(size_t)r0 * N + c0col] = v00; C[(size_t)r0 * N + c0col + 1] = v01; }
            if (r1 < M) { C[(size_t)r1 * N + c0col] = v10; C[(size_t)r1 * N + c0col + 1] = v11; }
        }
    }
}

// ---------------- padding for input GEMM ----------------
__global__ void pad_x(const float* __restrict__ x) {
    int idx = blockIdx.x * blockDim.x + threadIdx.x;
    if (idx >= NN * FINP) return;
    int n = idx / FINP, c2 = idx % FINP;
    g_xp[idx] = (c2 < FIN) ? x[(size_t)n * FIN + c2] : 0.f;
}
__global__ void pad_w(const float* __restrict__ w) {
    int idx = blockIdx.x * blockDim.x + threadIdx.x;
    if (idx >= FINP * HID) return;
    int k = idx / HID, j = idx % HID;
    g_wip[idx] = (k < FIN) ? w[(size_t)k * HID + j] : 0.f;
}

// ---------------- CSR build ----------------
__global__ void deg_kernel(const int* __restrict__ ei) {
    int e = blockIdx.x * blockDim.x + threadIdx.x;
    if (e >= ETOT) return;
    int t = (e < EE) ? ei[EE + e] : (e - EE);
    atomicAdd(&g_deg[t], 1);
}

__global__ void scan_kernel() {
    __shared__ int sh[1024];
    __shared__ int running;
    if (threadIdx.x == 0) running = 0;
    __syncthreads();
    for (int base = 0; base < NN; base += 1024) {
        int i = base + (int)threadIdx.x;
        int v = (i < NN) ? g_deg[i] : 0;
        sh[threadIdx.x] = v;
        __syncthreads();
        for (int off = 1; off < 1024; off <<= 1) {
            int t = (threadIdx.x >= off) ? sh[threadIdx.x - off] : 0;
            __syncthreads();
            sh[threadIdx.x] += t;
            __syncthreads();
        }
        int incl = sh[threadIdx.x];
        int excl = incl - v + running;
        if (i < NN) { g_rowptr[i] = excl; g_wpos[i] = excl; }
        __syncthreads();
        if (threadIdx.x == 0) running += sh[1023];
        __syncthreads();
    }
    if (threadIdx.x == 0) g_rowptr[NN] = running;
}

__global__ void scatter_kernel(const int* __restrict__ ei) {
    int e = blockIdx.x * blockDim.x + threadIdx.x;
    if (e >= ETOT) return;
    int s = (e < EE) ? ei[e]      : (e - EE);
    int t = (e < EE) ? ei[EE + e] : (e - EE);
    int slot = atomicAdd(&g_wpos[t], 1);
    g_esrc[slot] = s;
}

// ---------------- per-(node,head) attention scores ----------------
__global__ void scores_kernel(const float* __restrict__ feat, int fstride,
                              const float* __restrict__ asrc,
                              const float* __restrict__ adst,
                              int d, int slice) {
    int gt   = blockIdx.x * blockDim.x + threadIdx.x;
    int warp = gt >> 5;
    int lane = gt & 31;
    if (warp >= NN * NHEADS) return;
    int n = warp / NHEADS, h = warp % NHEADS;
    const float* row = feat + (size_t)n * fstride + (slice ? h * d : 0);
    float s1 = 0.f, s2 = 0.f;
    for (int i = lane; i < d; i += 32) {
        float v = row[i];
        s1 += v * asrc[h * d + i];
        s2 += v * adst[h * d + i];
    }
#pragma unroll
    for (int o = 16; o; o >>= 1) {
        s1 += __shfl_xor_sync(0xFFFFFFFFu, s1, o);
        s2 += __shfl_xor_sync(0xFFFFFFFFu, s2, o);
    }
    if (lane == 0) {
        g_ssrc[n * NHEADS + h] = s1;
        g_sdst[n * NHEADS + h] = s2;
    }
}

// ---------------- segment softmax, atomic-free ----------------
__global__ void softmax_csr() {
    int idx = blockIdx.x * blockDim.x + threadIdx.x;
    if (idx >= NN * NHEADS) return;
    int n = idx / NHEADS, h = idx % NHEADS;
    int beg = g_rowptr[n], end = g_rowptr[n + 1];
    float sd = g_sdst[idx];
    float mx = -1e30f;
    for (int j = beg; j < end; j++) {
        float v = leaky(g_ssrc[g_esrc[j] * NHEADS + h] + sd);
        mx = fmaxf(mx, v);
    }
    float den = 0.f;
    for (int j = beg; j < end; j++) {
        float v  = leaky(g_ssrc[g_esrc[j] * NHEADS + h] + sd);
        float ex = expf(v - mx);
        g_alpha[(size_t)j * NHEADS + h] = ex;
        den += ex;
    }
    g_den[idx] = 1.f / den;
}

// ---------------- layers 0/1 aggregation (d=32), fused bias+ELU ---------
__global__ void __launch_bounds__(256)
aggr_csr_256(const float* __restrict__ bias) {
    int n   = blockIdx.x;
    int tid = threadIdx.x;
    int h   = tid >> 5;
    int beg = g_rowptr[n], end = g_rowptr[n + 1];
    float inv = g_den[n * NHEADS + h];
    float acc = 0.f;
    for (int j = beg; j < end; j++) {
        int   s  = g_esrc[j];
        float al = g_alpha[(size_t)j * NHEADS + h];
        acc += al * g_ht[(size_t)s * HID + tid];
    }
    float v = acc * inv + bias[tid];
    g_h[(size_t)n * HID + tid] = v > 0.f ? v : expm1f(v);
}

// ---------------- layer2: aggregate RAW x per head -> g_ht [N,2048] -----
__global__ void __launch_bounds__(256)
aggr2_raw() {
    int n   = blockIdx.x;
    int tid = threadIdx.x;
    int beg = g_rowptr[n], end = g_rowptr[n + 1];
    float acc[NHEADS];
#pragma unroll
    for (int k = 0; k < NHEADS; k++) acc[k] = 0.f;
    for (int j = beg; j < end; j++) {
        int s = g_esrc[j];
        float v = g_h[(size_t)s * HID + tid];
        const float* al = g_alpha + (size_t)j * NHEADS;
#pragma unroll
        for (int k = 0; k < NHEADS; k++) acc[k] += al[k] * v;
    }
#pragma unroll
    for (int k = 0; k < NHEADS; k++) {
        float inv = g_den[n * NHEADS + k];
        g_ht[(size_t)n * FMAX + k * HID + tid] = acc[k] * inv;
    }
}

// ---------------- layer2 pre-projection: u,v and W2' --------------------
__global__ void compute_uv(const float* __restrict__ w2,
                           const float* __restrict__ a_s,
                           const float* __restrict__ a_d) {
    int t = blockIdx.x * blockDim.x + threadIdx.x;
    if (t >= 2 * NHEADS * HID) return;
    int sel = t / (NHEADS * HID);
    int h = (t / HID) % NHEADS;
    int i = t % HID;
    const float* av   = (sel ? a_d : a_s) + h * HID;
    const float* wrow = w2 + (size_t)i * FMAX + h * HID;
    float s = 0.f;
    for (int j = 0; j < HID; j++) s += wrow[j] * av[j];
    (sel ? g_v : g_u)[h * HID + i] = s;
}

__global__ void transpose_b2(const float* __restrict__ w2) {
    int t = blockIdx.x * blockDim.x + threadIdx.x;
    if (t >= FMAX * HID) return;
    int k = t / HID;          // h*256 + i
    int j = t % HID;
    int h = k / HID, i = k % HID;
    g_b2t[t] = w2[(size_t)i * FMAX + h * HID + j] * 0.125f;
}

// ---------------- classifier tail ----------------
__global__ void classifier2(const float* __restrict__ wc2,
                            const float* __restrict__ bc2,
                            float* __restrict__ out) {
    int n = blockIdx.x * blockDim.x + threadIdx.x;
    if (n >= NN) return;
    float a0 = bc2[0], a1 = bc2[1];
    const float* r = g_c1 + (size_t)n * 128;
#pragma unroll 4
    for (int k = 0; k < 128; k++) {
        float v = r[k];
        a0 += v * wc2[k * 2 + 0];
        a1 += v * wc2[k * 2 + 1];
    }
    out[n * 2 + 0] = a0;
    out[n * 2 + 1] = a1;
}

// ---------------- host orchestration ----------------
static inline void launch_gemm(const float* A, const float* B, float* C,
                               int M, int K, int N, const float* bias, int act,
                               int terms) {
    dim3 grid(N / BN, (M + BM - 1) / BM);
    if (terms == 3)
        gemm_tf32x3<<<grid, 256>>>(A, B, C, M, K, N, bias, act);
    else
        gemm_tf32x1<<<grid, 256>>>(A, B, C, M, K, N, bias, act);
}

extern "C" void kernel_launch(void* const* d_in, const int* in_sizes, int n_in,
                              void* d_out, int out_size) {
    const float* x     = (const float*)d_in[0];
    const int*   ei    = (const int*)  d_in[1];
    const float* w_in  = (const float*)d_in[2];
    const float* b_in  = (const float*)d_in[3];
    const float* w0    = (const float*)d_in[4];
    const float* asrc0 = (const float*)d_in[5];
    const float* adst0 = (const float*)d_in[6];
    const float* b0    = (const float*)d_in[7];
    const float* w1    = (const float*)d_in[8];
    const float* asrc1 = (const float*)d_in[9];
    const float* adst1 = (const float*)d_in[10];
    const float* b1    = (const float*)d_in[11];
    const float* w2    = (const float*)d_in[12];
    const float* asrc2 = (const float*)d_in[13];
    const float* adst2 = (const float*)d_in[14];
    const float* b2    = (const float*)d_in[15];
    const float* wc1   = (const float*)d_in[16];
    const float* bc1   = (const float*)d_in[17];
    const float* wc2   = (const float*)d_in[18];
    const float* bc2   = (const float*)d_in[19];
    float* out = (float*)d_out;

    float *p_h, *p_ht, *p_c1, *p_b2t, *p_u, *p_v, *p_xp, *p_wip;
    int   *p_deg;
    cudaGetSymbolAddress((void**)&p_h,   g_h);
    cudaGetSymbolAddress((void**)&p_ht,  g_ht);
    cudaGetSymbolAddress((void**)&p_c1,  g_c1);
    cudaGetSymbolAddress((void**)&p_b2t, g_b2t);
    cudaGetSymbolAddress((void**)&p_u,   g_u);
    cudaGetSymbolAddress((void**)&p_v,   g_v);
    cudaGetSymbolAddress((void**)&p_xp,  g_xp);
    cudaGetSymbolAddress((void**)&p_wip, g_wip);
    cudaGetSymbolAddress((void**)&p_deg, g_deg);

    // ---- CSR build (once; reused by all 3 layers) ----
    cudaMemsetAsync(p_deg, 0, NN * sizeof(int));
    deg_kernel<<<(ETOT + 255) / 256, 256>>>(ei);
    scan_kernel<<<1, 1024>>>();
    scatter_kernel<<<(ETOT + 255) / 256, 256>>>(ei);

    // ---- input linear (padded to K=176), accurate ----
    pad_x<<<(NN * FINP + 255) / 256, 256>>>(x);
    pad_w<<<(FINP * HID + 255) / 256, 256>>>(w_in);
    launch_gemm(p_xp, p_wip, p_h, NN, FINP, HID, b_in, 0, 3);

    const unsigned score_grid = (unsigned)(((long)NN * NHEADS * 32 + 255) / 256);

    // ---- layers 0 and 1 (accurate transforms) ----
    const float* Ws[2]  = {w0, w1};
    const float* As_[2] = {asrc0, asrc1};
    const float* Ad_[2] = {adst0, adst1};
    const float* Bs_[2] = {b0, b1};
    for (int l = 0; l < 2; l++) {
        launch_gemm(p_h, Ws[l], p_ht, NN, HID, HID, nullptr, 0, 3);
        scores_kernel<<<score_grid, 256>>>(p_ht, HID, As_[l], Ad_[l],
                                           HID / NHEADS, 1);
        softmax_csr<<<(NN * NHEADS + 255) / 256, 256>>>();
        aggr_csr_256<<<NN, 256>>>(Bs_[l]);
    }

    // ---- layer 2 (aggregate raw x; K=2048 GEMM in single-tf32 fast path) ----
    compute_uv<<<(2 * NHEADS * HID + 255) / 256, 256>>>(w2, asrc2, adst2);
    transpose_b2<<<(FMAX * HID + 255) / 256, 256>>>(w2);
    scores_kernel<<<score_grid, 256>>>(p_h, HID, p_u, p_v, HID, 0);
    softmax_csr<<<(NN * NHEADS + 255) / 256, 256>>>();
    aggr2_raw<<<NN, 256>>>();
    launch_gemm(p_ht, p_b2t, p_h, NN, FMAX, HID, b2, 0, 1);

    // ---- classifier (accurate) ----
    launch_gemm(p_h, wc1, p_c1, NN, HID, 128, bc1, 1, 3);
    classifier2<<<(NN + 255) / 256, 256>>>(wc2, bc2, out);
}